// round 1
// baseline (speedup 1.0000x reference)
#include <cuda_runtime.h>
#include <cstdint>

#define DD   512
#define LL   128
#define HALF 4096
#define MROWS 8192

// Scratch (static __device__ — no allocations allowed)
__device__ float g_P[MROWS * 1024];   // [8192][1024]: cols 0..511 = X@Wq+bq, 512..1023 = X@Wc
__device__ float g_G[MROWS * 1024];   // [8192][1024]: cols 0..511 = context c, 512..1023 = source X
__device__ float g_O[MROWS * 512];    // pre-mix attention outputs (rows 0..4095 = a1, 4096.. = a2)

__device__ __forceinline__ uint32_t f2tf32(float x) {
    uint32_t r; asm("cvt.rna.tf32.f32 %0, %1;" : "=r"(r) : "f"(x)); return r;
}

__device__ __forceinline__ void mma_tf32(float* d, const uint32_t* a, const uint32_t* b) {
    asm volatile(
        "mma.sync.aligned.m16n8k8.row.col.f32.tf32.tf32.f32 "
        "{%0,%1,%2,%3}, {%4,%5,%6,%7}, {%8,%9}, {%0,%1,%2,%3};"
        : "+f"(d[0]), "+f"(d[1]), "+f"(d[2]), "+f"(d[3])
        : "r"(a[0]), "r"(a[1]), "r"(a[2]), "r"(a[3]), "r"(b[0]), "r"(b[1]));
}

// ---------------------------------------------------------------------------
// tf32 GEMM: C[M,N] = A[M,K] @ B[K,N] (+ bias[n] for n<512)
// A rows: row<M0 -> A0, else A1 (virtual stacking), row stride = K.
// B cols: n<512 -> B0[k*512+n], else B1[k*512+n-512].
// MODE 0: C = g_P (projection). MODE 1: A = g_G, C = g_O (output gemm).
// CTA tile 128x64, BK=32, 8 warps (warp tile 32x32).
// ---------------------------------------------------------------------------
template<int MODE>
__global__ __launch_bounds__(256) void gemm_tf32_kernel(
    const float* __restrict__ A0in, const float* __restrict__ A1in, int M0,
    const float* __restrict__ B0, const float* __restrict__ B1,
    const float* __restrict__ bias,
    int M, int N, int K)
{
    constexpr int BM = 128, BN = 64, BK = 32;
    constexpr int LDA = BK + 4;   // 36: conflict-free frag loads, 16B-aligned rows
    constexpr int LDB = BN + 8;   // 72: conflict-free frag loads

    __shared__ uint32_t As[BM * LDA];
    __shared__ uint32_t Bs[BK * LDB];

    float* C = (MODE == 0) ? g_P : g_O;
    const float* A0 = (MODE == 0) ? A0in : (const float*)g_G;
    const float* A1 = (MODE == 0) ? A1in : (const float*)g_G;

    const int m0 = blockIdx.y * BM;
    const int n0 = blockIdx.x * BN;
    const int tid = threadIdx.x;
    const int warp = tid >> 5, lane = tid & 31;
    const int wm = (warp >> 1) * 32;
    const int wn = (warp & 1) * 32;

    float acc[2][4][4];
    #pragma unroll
    for (int i = 0; i < 2; i++)
        #pragma unroll
        for (int j = 0; j < 4; j++)
            #pragma unroll
            for (int k = 0; k < 4; k++) acc[i][j][k] = 0.f;

    for (int k0 = 0; k0 < K; k0 += BK) {
        // Load A tile: 128x32 f32 = 1024 float4
        #pragma unroll
        for (int it = 0; it < (BM * BK / 4) / 256; it++) {
            int i = tid + it * 256;
            int r  = i >> 3;          // 8 float4 per row
            int c4 = (i & 7) * 4;
            int row = m0 + r;
            const float* ap = (row < M0) ? (A0 + (size_t)row * K)
                                         : (A1 + (size_t)(row - M0) * K);
            float4 va = *(const float4*)(ap + k0 + c4);
            uint32_t* dst = &As[r * LDA + c4];
            dst[0] = f2tf32(va.x); dst[1] = f2tf32(va.y);
            dst[2] = f2tf32(va.z); dst[3] = f2tf32(va.w);
        }
        // Load B tile: 32x64 f32 = 512 float4
        #pragma unroll
        for (int it = 0; it < (BK * BN / 4) / 256; it++) {
            int i = tid + it * 256;
            int r  = i >> 4;          // 16 float4 per row
            int c4 = (i & 15) * 4;
            int k = k0 + r;
            int n = n0 + c4;
            const float* bp = (n < 512) ? (B0 + (size_t)k * 512 + n)
                                        : (B1 + (size_t)k * 512 + (n - 512));
            float4 vb = *(const float4*)bp;
            uint32_t* dst = &Bs[r * LDB + c4];
            dst[0] = f2tf32(vb.x); dst[1] = f2tf32(vb.y);
            dst[2] = f2tf32(vb.z); dst[3] = f2tf32(vb.w);
        }
        __syncthreads();

        #pragma unroll
        for (int ks = 0; ks < BK / 8; ks++) {
            const int kk = ks * 8;
            uint32_t af[2][4], bf[4][2];
            #pragma unroll
            for (int mf = 0; mf < 2; mf++) {
                int r = wm + mf * 16 + (lane >> 2);
                int c = kk + (lane & 3);
                af[mf][0] = As[r * LDA + c];
                af[mf][1] = As[(r + 8) * LDA + c];
                af[mf][2] = As[r * LDA + c + 4];
                af[mf][3] = As[(r + 8) * LDA + c + 4];
            }
            #pragma unroll
            for (int nf = 0; nf < 4; nf++) {
                int c = wn + nf * 8 + (lane >> 2);
                int r = kk + (lane & 3);
                bf[nf][0] = Bs[r * LDB + c];
                bf[nf][1] = Bs[(r + 4) * LDB + c];
            }
            #pragma unroll
            for (int mf = 0; mf < 2; mf++)
                #pragma unroll
                for (int nf = 0; nf < 4; nf++)
                    mma_tf32(acc[mf][nf], af[mf], bf[nf]);
        }
        __syncthreads();
    }

    // Epilogue
    #pragma unroll
    for (int mf = 0; mf < 2; mf++) {
        #pragma unroll
        for (int nf = 0; nf < 4; nf++) {
            int row = m0 + wm + mf * 16 + (lane >> 2);
            int col = n0 + wn + nf * 8 + (lane & 3) * 2;
            float b0v = (col < 512) ? bias[col] : 0.f;
            float b1v = (col + 1 < 512) ? bias[col + 1] : 0.f;
            C[(size_t)row * N + col]           = acc[mf][nf][0] + b0v;
            C[(size_t)row * N + col + 1]       = acc[mf][nf][1] + b1v;
            C[(size_t)(row + 8) * N + col]     = acc[mf][nf][2] + b0v;
            C[(size_t)(row + 8) * N + col + 1] = acc[mf][nf][3] + b1v;
        }
    }
}

// ---------------------------------------------------------------------------
// Fused scores (v . tanh(wq+uh)) + softmax + context. One CTA = 16 t-rows of
// one (call, b). Writes context into g_G cols 0..511.
// ---------------------------------------------------------------------------
#define SC_SMEM ((16*512 + 32*512 + 16*128) * 4)

__global__ __launch_bounds__(256) void score_ctx_kernel(
    const float* __restrict__ cur, const float* __restrict__ nobs,
    const float* __restrict__ v)
{
    extern __shared__ float sm[];
    float* wq_s = sm;                       // [16][512]
    float* uh_s = sm + 16 * 512;            // [32][512]
    float* sc_s = sm + 16 * 512 + 32 * 512; // [16][128]

    const int bid  = blockIdx.x;            // 512 blocks
    const int call = bid >> 8;              // 0: a1 (src=new_obs), 1: a2 (src=cur)
    const int b    = (bid >> 3) & 31;
    const int t0   = (bid & 7) * 16;
    const int tid  = threadIdx.x, warp = tid >> 5, lane = tid & 31;

    float vr[16];
    #pragma unroll
    for (int j = 0; j < 16; j++) vr[j] = v[lane + 32 * j];

    // wq rows: P[src_row][0:512]
    const int srcbase = call * HALF + b * LL + t0;
    for (int i = tid; i < 16 * 128; i += 256) {         // float4 items
        int r = i >> 7; int c4 = (i & 127) * 4;
        float4 x = *(const float4*)(g_P + (size_t)(srcbase + r) * 1024 + c4);
        *(float4*)(wq_s + r * 512 + c4) = x;
    }
    const int membase = (1 - call) * HALF + b * LL;

    // scores over 4 s-tiles of 32
    for (int st = 0; st < 4; st++) {
        __syncthreads();  // prior compute done (and wq stores visible on st=0)
        for (int i = tid; i < 32 * 128; i += 256) {
            int r = i >> 7; int c4 = (i & 127) * 4;
            float4 x = *(const float4*)(g_P + (size_t)(membase + st * 32 + r) * 1024 + 512 + c4);
            *(float4*)(uh_s + r * 512 + c4) = x;
        }
        __syncthreads();

        #pragma unroll
        for (int ti = 0; ti < 2; ti++) {
            const int t = warp * 2 + ti;
            float wqr[16];
            #pragma unroll
            for (int j = 0; j < 16; j++) wqr[j] = wq_s[t * 512 + lane + 32 * j];
            for (int s = 0; s < 32; s++) {
                float acc = 0.f;
                #pragma unroll
                for (int j = 0; j < 16; j++) {
                    float x = wqr[j] + uh_s[s * 512 + lane + 32 * j];
                    float th; asm("tanh.approx.f32 %0, %1;" : "=f"(th) : "f"(x));
                    acc = fmaf(vr[j], th, acc);
                }
                #pragma unroll
                for (int o = 16; o > 0; o >>= 1)
                    acc += __shfl_xor_sync(0xffffffffu, acc, o);
                if (lane == 0) sc_s[t * 128 + st * 32 + s] = acc;
            }
        }
    }
    __syncthreads();

    // softmax per t-row (warp w owns rows 2w, 2w+1)
    #pragma unroll
    for (int ti = 0; ti < 2; ti++) {
        const int t = warp * 2 + ti;
        float x0[4]; float mx = -1e30f;
        #pragma unroll
        for (int j = 0; j < 4; j++) {
            x0[j] = sc_s[t * 128 + lane + 32 * j];
            mx = fmaxf(mx, x0[j]);
        }
        #pragma unroll
        for (int o = 16; o > 0; o >>= 1)
            mx = fmaxf(mx, __shfl_xor_sync(0xffffffffu, mx, o));
        float sum = 0.f;
        #pragma unroll
        for (int j = 0; j < 4; j++) { x0[j] = __expf(x0[j] - mx); sum += x0[j]; }
        #pragma unroll
        for (int o = 16; o > 0; o >>= 1)
            sum += __shfl_xor_sync(0xffffffffu, sum, o);
        float inv = 1.0f / sum;
        #pragma unroll
        for (int j = 0; j < 4; j++) sc_s[t * 128 + lane + 32 * j] = x0[j] * inv;
    }
    __syncthreads();

    // context: c[16][512] = align @ memory  (memory = raw input tensor)
    const float* mem = ((call == 0) ? cur : nobs) + (size_t)b * LL * DD;
    const int g  = tid >> 7;            // t-half 0/1
    const int dt = (tid & 127) * 4;     // d base
    float a4[8][4];
    #pragma unroll
    for (int tt = 0; tt < 8; tt++)
        #pragma unroll
        for (int k = 0; k < 4; k++) a4[tt][k] = 0.f;

    for (int s = 0; s < 128; s++) {
        float4 mv = *(const float4*)(mem + (size_t)s * DD + dt);
        #pragma unroll
        for (int tt = 0; tt < 8; tt++) {
            float al = sc_s[(g * 8 + tt) * 128 + s];
            a4[tt][0] = fmaf(al, mv.x, a4[tt][0]);
            a4[tt][1] = fmaf(al, mv.y, a4[tt][1]);
            a4[tt][2] = fmaf(al, mv.z, a4[tt][2]);
            a4[tt][3] = fmaf(al, mv.w, a4[tt][3]);
        }
    }
    #pragma unroll
    for (int tt = 0; tt < 8; tt++) {
        int t = g * 8 + tt;
        float4 o = make_float4(a4[tt][0], a4[tt][1], a4[tt][2], a4[tt][3]);
        *(float4*)(g_G + (size_t)(call * HALF + b * LL + t0 + t) * 1024 + dt) = o;
    }
}

// Copy source X into g_G cols 512..1023 (rows: [new_obs; current_sotw])
__global__ __launch_bounds__(256) void copy_src_kernel(
    const float* __restrict__ cur, const float* __restrict__ nobs)
{
    int i = blockIdx.x * blockDim.x + threadIdx.x;  // 1,048,576 float4 items
    int r  = i >> 7;
    int c4 = (i & 127) * 4;
    const float* X = (r < HALF) ? (nobs + (size_t)r * DD)
                                : (cur + (size_t)(r - HALF) * DD);
    float4 x = *(const float4*)(X + c4);
    *(float4*)(g_G + (size_t)r * 1024 + 512 + c4) = x;
}

// out = (1-m)*a1 + m*a2
__global__ __launch_bounds__(256) void combine_kernel(
    const float* __restrict__ mix, float* __restrict__ out)
{
    int i = blockIdx.x * blockDim.x + threadIdx.x;  // 524,288 float4 items
    float m = __ldg(mix);
    float4 a = *(const float4*)(g_O + (size_t)4 * i);
    float4 b = *(const float4*)(g_O + (size_t)4 * i + (size_t)HALF * 512);
    float4 o;
    o.x = (1.f - m) * a.x + m * b.x;
    o.y = (1.f - m) * a.y + m * b.y;
    o.z = (1.f - m) * a.z + m * b.z;
    o.w = (1.f - m) * a.w + m * b.w;
    *(float4*)(out + (size_t)4 * i) = o;
}

extern "C" void kernel_launch(void* const* d_in, const int* in_sizes, int n_in,
                              void* d_out, int out_size)
{
    const float* cur  = (const float*)d_in[0];  // current_sotw [32,128,512]
    const float* nobs = (const float*)d_in[1];  // new_obs      [32,128,512]
    const float* Wq   = (const float*)d_in[2];
    const float* bq   = (const float*)d_in[3];
    const float* Wc   = (const float*)d_in[4];
    const float* v    = (const float*)d_in[5];
    const float* Wout = (const float*)d_in[6];
    const float* bout = (const float*)d_in[7];
    const float* mix  = (const float*)d_in[8];
    float* out = (float*)d_out;

    cudaFuncSetAttribute(score_ctx_kernel,
                         cudaFuncAttributeMaxDynamicSharedMemorySize, SC_SMEM);

    // 1) Projections: g_P = [new_obs; cur] @ [Wq | Wc] (+bq on q-half)
    gemm_tf32_kernel<0><<<dim3(16, 64), 256>>>(nobs, cur, HALF, Wq, Wc, bq,
                                               MROWS, 1024, 512);
    // 2) Stage source copy into g_G right half
    copy_src_kernel<<<4096, 256>>>(cur, nobs);
    // 3) Scores + softmax + context -> g_G left half
    score_ctx_kernel<<<512, 256, SC_SMEM>>>(cur, nobs, v);
    // 4) Output GEMM: g_O = g_G @ Wout + bout
    gemm_tf32_kernel<1><<<dim3(8, 64), 256>>>(nullptr, nullptr, MROWS, Wout, Wout,
                                              bout, MROWS, 512, 1024);
    // 5) Mix combine
    combine_kernel<<<2048, 256>>>(mix, out);
}

// round 2
// speedup vs baseline: 1.2217x; 1.2217x over previous
#include <cuda_runtime.h>
#include <cuda_fp16.h>
#include <cstdint>

#define DD   512
#define LL   128
#define HALF 4096
#define MROWS 8192

// Scratch
__device__ uint32_t g_Pu[MROWS * 512];    // half2-packed projections: cols 0..255 = wq, 256..511 = uh (per row 1024 halfs)
__device__ float    g_ZS[MROWS * 1024];   // cols 0..511: Z = X@Wout_top (tf32-rounded), 512..1023: S = X@Wout_bot (f32)
__device__ float    g_O [2 * HALF * 512]; // align @ Z per call

__device__ __forceinline__ uint32_t f2tf32(float x) {
    uint32_t r; asm("cvt.rna.tf32.f32 %0, %1;" : "=r"(r) : "f"(x)); return r;
}
__device__ __forceinline__ void mma_tf32(float* d, const uint32_t* a, const uint32_t* b) {
    asm volatile(
        "mma.sync.aligned.m16n8k8.row.col.f32.tf32.tf32.f32 "
        "{%0,%1,%2,%3}, {%4,%5,%6,%7}, {%8,%9}, {%0,%1,%2,%3};"
        : "+f"(d[0]), "+f"(d[1]), "+f"(d[2]), "+f"(d[3])
        : "r"(a[0]), "r"(a[1]), "r"(a[2]), "r"(a[3]), "r"(b[0]), "r"(b[1]));
}
__device__ __forceinline__ uint32_t hadd2u(uint32_t a, uint32_t b) {
    uint32_t r; asm("add.rn.f16x2 %0,%1,%2;" : "=r"(r) : "r"(a), "r"(b)); return r;
}
__device__ __forceinline__ uint32_t tanh2u(uint32_t a) {
    uint32_t r; asm("tanh.approx.f16x2 %0,%1;" : "=r"(r) : "r"(a)); return r;
}
__device__ __forceinline__ uint32_t hfma2u(uint32_t a, uint32_t b, uint32_t c) {
    uint32_t r; asm("fma.rn.f16x2 %0,%1,%2,%3;" : "=r"(r) : "r"(a), "r"(b), "r"(c)); return r;
}
__device__ __forceinline__ float h2sum(uint32_t u) {
    __half2 h = *reinterpret_cast<__half2*>(&u);
    float2 f = __half22float2(h);
    return f.x + f.y;
}

// ---------------------------------------------------------------------------
// tf32 GEMM, M=8192 N=1024 K=512, double-buffered.
// A rows: row<4096 -> A0 (new_obs), else A1 (cur). B cols: n0<512 -> B0, else B1.
// MODE 0: projections -> g_Pu as half2 (+bq on n<512)
// MODE 1: Z|S -> g_ZS (n<512 stored tf32-rounded, n>=512 raw f32)
// CTA tile 128x64, BK=32, 8 warps (4m x 2n), warp tile 32x32.
// ---------------------------------------------------------------------------
#define GSMEM ((2*128*36 + 2*32*72) * 4)

template<int MODE>
__global__ void __launch_bounds__(256, 2) gemm_k(
    const float* __restrict__ A0, const float* __restrict__ A1,
    const float* __restrict__ B0, const float* __restrict__ B1,
    const float* __restrict__ bias)
{
    constexpr int BM = 128, BN = 64, LDA = 36, LDB = 72;
    extern __shared__ uint32_t sm[];
    uint32_t* As = sm;                  // [2][BM*LDA]
    uint32_t* Bs = sm + 2 * BM * LDA;   // [2][32*LDB]

    const int m0 = blockIdx.y * BM, n0 = blockIdx.x * BN;
    const int tid = threadIdx.x, warp = tid >> 5, lane = tid & 31;
    const int wm = (warp >> 1) * 32, wn = (warp & 1) * 32;

    const float* Bp = (n0 < 512) ? (B0 + n0) : (B1 + (n0 - 512));

    float acc[2][4][4];
    #pragma unroll
    for (int i = 0; i < 2; i++)
        #pragma unroll
        for (int j = 0; j < 4; j++)
            #pragma unroll
            for (int k = 0; k < 4; k++) acc[i][j][k] = 0.f;

    // A/B staging addresses
    const int aidx_r  = tid >> 3;          // +32 per it
    const int aidx_c4 = (tid & 7) * 4;
    const int bidx_r  = tid >> 4;          // +16 per it
    const int bidx_c4 = (tid & 15) * 4;

    float4 ra[4], rb[2];

    // prologue: load ktile 0
    #pragma unroll
    for (int it = 0; it < 4; it++) {
        int row = m0 + aidx_r + it * 32;
        const float* ap = (row < HALF) ? (A0 + (size_t)row * 512)
                                       : (A1 + (size_t)(row - HALF) * 512);
        ra[it] = *(const float4*)(ap + aidx_c4);
    }
    #pragma unroll
    for (int it = 0; it < 2; it++)
        rb[it] = *(const float4*)(Bp + (size_t)(bidx_r + it * 16) * 512 + bidx_c4);

    #pragma unroll
    for (int it = 0; it < 4; it++) {
        uint32_t* d = &As[(aidx_r + it * 32) * LDA + aidx_c4];
        d[0] = f2tf32(ra[it].x); d[1] = f2tf32(ra[it].y);
        d[2] = f2tf32(ra[it].z); d[3] = f2tf32(ra[it].w);
    }
    #pragma unroll
    for (int it = 0; it < 2; it++) {
        uint32_t* d = &Bs[(bidx_r + it * 16) * LDB + bidx_c4];
        d[0] = f2tf32(rb[it].x); d[1] = f2tf32(rb[it].y);
        d[2] = f2tf32(rb[it].z); d[3] = f2tf32(rb[it].w);
    }
    __syncthreads();

    for (int kt = 0; kt < 16; kt++) {
        const int buf = kt & 1;
        if (kt < 15) {
            const int k0 = (kt + 1) * 32;
            #pragma unroll
            for (int it = 0; it < 4; it++) {
                int row = m0 + aidx_r + it * 32;
                const float* ap = (row < HALF) ? (A0 + (size_t)row * 512)
                                               : (A1 + (size_t)(row - HALF) * 512);
                ra[it] = *(const float4*)(ap + k0 + aidx_c4);
            }
            #pragma unroll
            for (int it = 0; it < 2; it++)
                rb[it] = *(const float4*)(Bp + (size_t)(k0 + bidx_r + it * 16) * 512 + bidx_c4);
        }

        const uint32_t* Ab = As + buf * BM * LDA;
        const uint32_t* Bb = Bs + buf * 32 * LDB;
        #pragma unroll
        for (int ks = 0; ks < 4; ks++) {
            const int kk = ks * 8;
            uint32_t af[2][4], bf[4][2];
            #pragma unroll
            for (int mf = 0; mf < 2; mf++) {
                int r = wm + mf * 16 + (lane >> 2);
                int c = kk + (lane & 3);
                af[mf][0] = Ab[r * LDA + c];
                af[mf][1] = Ab[(r + 8) * LDA + c];
                af[mf][2] = Ab[r * LDA + c + 4];
                af[mf][3] = Ab[(r + 8) * LDA + c + 4];
            }
            #pragma unroll
            for (int nf = 0; nf < 4; nf++) {
                int c = wn + nf * 8 + (lane >> 2);
                int r = kk + (lane & 3);
                bf[nf][0] = Bb[r * LDB + c];
                bf[nf][1] = Bb[(r + 4) * LDB + c];
            }
            #pragma unroll
            for (int mf = 0; mf < 2; mf++)
                #pragma unroll
                for (int nf = 0; nf < 4; nf++)
                    mma_tf32(acc[mf][nf], af[mf], bf[nf]);
        }

        if (kt < 15) {
            uint32_t* An = As + (buf ^ 1) * BM * LDA;
            uint32_t* Bn = Bs + (buf ^ 1) * 32 * LDB;
            #pragma unroll
            for (int it = 0; it < 4; it++) {
                uint32_t* d = &An[(aidx_r + it * 32) * LDA + aidx_c4];
                d[0] = f2tf32(ra[it].x); d[1] = f2tf32(ra[it].y);
                d[2] = f2tf32(ra[it].z); d[3] = f2tf32(ra[it].w);
            }
            #pragma unroll
            for (int it = 0; it < 2; it++) {
                uint32_t* d = &Bn[(bidx_r + it * 16) * LDB + bidx_c4];
                d[0] = f2tf32(rb[it].x); d[1] = f2tf32(rb[it].y);
                d[2] = f2tf32(rb[it].z); d[3] = f2tf32(rb[it].w);
            }
            __syncthreads();
        }
    }

    // epilogue
    #pragma unroll
    for (int mf = 0; mf < 2; mf++) {
        #pragma unroll
        for (int nf = 0; nf < 4; nf++) {
            int row = m0 + wm + mf * 16 + (lane >> 2);
            int col = n0 + wn + nf * 8 + (lane & 3) * 2;
            if (MODE == 0) {
                float b0 = 0.f, b1 = 0.f;
                if (n0 < 512) { b0 = bias[col]; b1 = bias[col + 1]; }
                __half2 h0 = __floats2half2_rn(acc[mf][nf][0] + b0, acc[mf][nf][1] + b1);
                __half2 h1 = __floats2half2_rn(acc[mf][nf][2] + b0, acc[mf][nf][3] + b1);
                g_Pu[(size_t)row * 512 + (col >> 1)]       = *reinterpret_cast<uint32_t*>(&h0);
                g_Pu[(size_t)(row + 8) * 512 + (col >> 1)] = *reinterpret_cast<uint32_t*>(&h1);
            } else {
                float2 v0, v1;
                if (n0 < 512) {  // Z half: round to tf32 now (consumed by mma)
                    v0 = make_float2(__uint_as_float(f2tf32(acc[mf][nf][0])),
                                     __uint_as_float(f2tf32(acc[mf][nf][1])));
                    v1 = make_float2(__uint_as_float(f2tf32(acc[mf][nf][2])),
                                     __uint_as_float(f2tf32(acc[mf][nf][3])));
                } else {         // S half: keep f32
                    v0 = make_float2(acc[mf][nf][0], acc[mf][nf][1]);
                    v1 = make_float2(acc[mf][nf][2], acc[mf][nf][3]);
                }
                *(float2*)&g_ZS[(size_t)row * 1024 + col]       = v0;
                *(float2*)&g_ZS[(size_t)(row + 8) * 1024 + col] = v1;
            }
        }
    }
}

// ---------------------------------------------------------------------------
// Fused: scores (v . tanh(wq+uh), f16x2) + softmax + (align @ Z) via tf32 mma.
// CTA = 16 t-rows of one (call, b). 512 CTAs.
// ---------------------------------------------------------------------------
#define SC_SMEM ((48*256 + 16*132) * 4)   // 57600 B

__global__ void __launch_bounds__(256) score_ctx_kernel(const float* __restrict__ v)
{
    extern __shared__ float smf[];
    uint32_t* wq2 = (uint32_t*)smf;            // [16][256] half2
    uint32_t* uh2 = (uint32_t*)smf + 16 * 256; // [32][256] half2
    float*    sc  = smf + 48 * 256;            // [16][132] scores/align
    float*    Zs  = smf;                       // phase B reuse: [16][516]

    const int bid  = blockIdx.x;
    const int call = bid >> 8;
    const int b    = (bid >> 3) & 31;
    const int t0   = (bid & 7) * 16;
    const int tid  = threadIdx.x, warp = tid >> 5, lane = tid & 31;

    const int srcbase = call * HALF + b * LL + t0;       // source rows (wq)
    const int membase = (1 - call) * HALF + b * LL;      // memory rows (uh, Z)

    // v as half2, layout: pair index p = lane*8 + j  (covers d = 2p, 2p+1)
    uint32_t v2[8];
    #pragma unroll
    for (int j = 0; j < 8; j++) {
        float2 vv = *(const float2*)(v + 2 * (lane * 8 + j));
        __half2 h = __floats2half2_rn(vv.x, vv.y);
        v2[j] = *reinterpret_cast<uint32_t*>(&h);
    }

    // stage wq (half2): 16 rows x 256 u32
    #pragma unroll
    for (int it = 0; it < 4; it++) {
        int idx = tid + it * 256;
        int r = idx >> 6, c4 = (idx & 63) * 4;
        *(uint4*)&wq2[r * 256 + c4] = *(const uint4*)&g_Pu[(size_t)(srcbase + r) * 512 + c4];
    }

    // -------- phase A: scores --------
    for (int st = 0; st < 4; st++) {
        __syncthreads();
        #pragma unroll
        for (int it = 0; it < 8; it++) {
            int idx = tid + it * 256;
            int r = idx >> 6, c4 = (idx & 63) * 4;
            *(uint4*)&uh2[r * 256 + c4] =
                *(const uint4*)&g_Pu[(size_t)(membase + st * 32 + r) * 512 + 256 + c4];
        }
        __syncthreads();

        #pragma unroll
        for (int ti = 0; ti < 2; ti++) {
            const int t = warp * 2 + ti;
            uint4 wA = *(uint4*)&wq2[t * 256 + lane * 8];
            uint4 wB = *(uint4*)&wq2[t * 256 + lane * 8 + 4];
            for (int s = 0; s < 32; s++) {
                uint4 uA = *(uint4*)&uh2[s * 256 + lane * 8];
                uint4 uB = *(uint4*)&uh2[s * 256 + lane * 8 + 4];
                uint32_t a2 = 0;
                a2 = hfma2u(v2[0], tanh2u(hadd2u(wA.x, uA.x)), a2);
                a2 = hfma2u(v2[1], tanh2u(hadd2u(wA.y, uA.y)), a2);
                a2 = hfma2u(v2[2], tanh2u(hadd2u(wA.z, uA.z)), a2);
                a2 = hfma2u(v2[3], tanh2u(hadd2u(wA.w, uA.w)), a2);
                float acc = h2sum(a2);
                a2 = 0;
                a2 = hfma2u(v2[4], tanh2u(hadd2u(wB.x, uB.x)), a2);
                a2 = hfma2u(v2[5], tanh2u(hadd2u(wB.y, uB.y)), a2);
                a2 = hfma2u(v2[6], tanh2u(hadd2u(wB.z, uB.z)), a2);
                a2 = hfma2u(v2[7], tanh2u(hadd2u(wB.w, uB.w)), a2);
                acc += h2sum(a2);
                #pragma unroll
                for (int o = 16; o > 0; o >>= 1)
                    acc += __shfl_xor_sync(0xffffffffu, acc, o);
                if (lane == 0) sc[t * 132 + st * 32 + s] = acc;
            }
        }
    }
    __syncwarp();

    // -------- softmax per t-row (store align as tf32 bits) --------
    #pragma unroll
    for (int ti = 0; ti < 2; ti++) {
        const int t = warp * 2 + ti;
        float x0[4]; float mx = -1e30f;
        #pragma unroll
        for (int j = 0; j < 4; j++) {
            x0[j] = sc[t * 132 + lane + 32 * j];
            mx = fmaxf(mx, x0[j]);
        }
        #pragma unroll
        for (int o = 16; o > 0; o >>= 1)
            mx = fmaxf(mx, __shfl_xor_sync(0xffffffffu, mx, o));
        float sum = 0.f;
        #pragma unroll
        for (int j = 0; j < 4; j++) { x0[j] = __expf(x0[j] - mx); sum += x0[j]; }
        #pragma unroll
        for (int o = 16; o > 0; o >>= 1)
            sum += __shfl_xor_sync(0xffffffffu, sum, o);
        float inv = 1.0f / sum;
        #pragma unroll
        for (int j = 0; j < 4; j++)
            sc[t * 132 + lane + 32 * j] = __uint_as_float(f2tf32(x0[j] * inv));
    }

    // -------- phase B: out_part[16][512] = align @ Z via tf32 mma --------
    float accB[8][4];
    #pragma unroll
    for (int nf = 0; nf < 8; nf++)
        #pragma unroll
        for (int k = 0; k < 4; k++) accB[nf][k] = 0.f;

    const int ncol = warp * 64;
    const int mrow = lane >> 2;

    for (int kc = 0; kc < 8; kc++) {
        __syncthreads();   // uh2/wq2 (or prev Zs) free; also orders softmax before A-frag reads
        #pragma unroll
        for (int it = 0; it < 8; it++) {
            int idx = tid + it * 256;
            int r = idx >> 7, c4 = (idx & 127) * 4;
            *(float4*)&Zs[r * 516 + c4] =
                *(const float4*)&g_ZS[(size_t)(membase + kc * 16 + r) * 1024 + c4];
        }
        __syncthreads();

        #pragma unroll
        for (int kf = 0; kf < 2; kf++) {
            const int k8 = kc * 2 + kf;
            const int scol = k8 * 8 + (lane & 3);
            uint32_t af[4];
            af[0] = __float_as_uint(sc[mrow * 132 + scol]);
            af[1] = __float_as_uint(sc[(mrow + 8) * 132 + scol]);
            af[2] = __float_as_uint(sc[mrow * 132 + scol + 4]);
            af[3] = __float_as_uint(sc[(mrow + 8) * 132 + scol + 4]);
            const int rk = kf * 8 + (lane & 3);
            #pragma unroll
            for (int nf = 0; nf < 8; nf++) {
                const int c = ncol + nf * 8 + (lane >> 2);
                uint32_t bf[2];
                bf[0] = __float_as_uint(Zs[rk * 516 + c]);
                bf[1] = __float_as_uint(Zs[(rk + 4) * 516 + c]);
                mma_tf32(accB[nf], af, bf);
            }
        }
    }

    // epilogue -> g_O
    const size_t base = (size_t)call * HALF + (size_t)b * LL + t0;
    #pragma unroll
    for (int nf = 0; nf < 8; nf++) {
        int c = ncol + nf * 8 + (lane & 3) * 2;
        *(float2*)&g_O[(base + mrow) * 512 + c]     = make_float2(accB[nf][0], accB[nf][1]);
        *(float2*)&g_O[(base + mrow + 8) * 512 + c] = make_float2(accB[nf][2], accB[nf][3]);
    }
}

// out = (1-m)*(O0 + S_nobs) + m*(O1 + S_cur) + bout
__global__ __launch_bounds__(256) void combine_kernel(
    const float* __restrict__ mix, const float* __restrict__ bout,
    float* __restrict__ out)
{
    int i = blockIdx.x * 256 + threadIdx.x;   // 524288 float4 items
    float m = __ldg(mix);
    int r = i >> 7, c4 = (i & 127) * 4;
    float4 o0 = *(float4*)&g_O[(size_t)r * 512 + c4];
    float4 o1 = *(float4*)&g_O[(size_t)(HALF + r) * 512 + c4];
    float4 s0 = *(const float4*)&g_ZS[(size_t)r * 1024 + 512 + c4];
    float4 s1 = *(const float4*)&g_ZS[(size_t)(HALF + r) * 1024 + 512 + c4];
    float4 bo = *(const float4*)(bout + c4);
    float4 o;
    float w0 = 1.f - m;
    o.x = w0 * (o0.x + s0.x) + m * (o1.x + s1.x) + bo.x;
    o.y = w0 * (o0.y + s0.y) + m * (o1.y + s1.y) + bo.y;
    o.z = w0 * (o0.z + s0.z) + m * (o1.z + s1.z) + bo.z;
    o.w = w0 * (o0.w + s0.w) + m * (o1.w + s1.w) + bo.w;
    *(float4*)(out + (size_t)4 * i) = o;
}

extern "C" void kernel_launch(void* const* d_in, const int* in_sizes, int n_in,
                              void* d_out, int out_size)
{
    const float* cur  = (const float*)d_in[0];
    const float* nobs = (const float*)d_in[1];
    const float* Wq   = (const float*)d_in[2];
    const float* bq   = (const float*)d_in[3];
    const float* Wc   = (const float*)d_in[4];
    const float* v    = (const float*)d_in[5];
    const float* Wout = (const float*)d_in[6];
    const float* bout = (const float*)d_in[7];
    const float* mix  = (const float*)d_in[8];
    float* out = (float*)d_out;

    cudaFuncSetAttribute(gemm_k<0>, cudaFuncAttributeMaxDynamicSharedMemorySize, GSMEM);
    cudaFuncSetAttribute(gemm_k<1>, cudaFuncAttributeMaxDynamicSharedMemorySize, GSMEM);
    cudaFuncSetAttribute(score_ctx_kernel, cudaFuncAttributeMaxDynamicSharedMemorySize, SC_SMEM);

    // 1) Projections: g_Pu = half2([nobs;cur] @ [Wq|Wc] + [bq|0])
    gemm_k<0><<<dim3(16, 64), 256, GSMEM>>>(nobs, cur, Wq, Wc, bq);
    // 2) Z|S: g_ZS = [nobs;cur] @ [Wout_top | Wout_bot]
    gemm_k<1><<<dim3(16, 64), 256, GSMEM>>>(nobs, cur, Wout, Wout + 512 * 512, nullptr);
    // 3) scores + softmax + align@Z
    score_ctx_kernel<<<512, 256, SC_SMEM>>>(v);
    // 4) mix + S + bias
    combine_kernel<<<2048, 256>>>(mix, bout, out);
}

// round 3
// speedup vs baseline: 1.4002x; 1.1461x over previous
#include <cuda_runtime.h>
#include <cuda_fp16.h>
#include <cstdint>

#define DD   512
#define LL   128
#define HALF 4096
#define MROWS 8192

// Scratch
__device__ uint32_t g_Pu[MROWS * 512];    // half2 projections: cols 0..255 wq, 256..511 uh
__device__ float    g_ZS[MROWS * 1024];   // cols 0..511 Z=X@Wout_top (tf32), 512..1023 S=X@Wout_bot (f32)
__device__ float    g_O [2 * HALF * 512]; // align @ Z per call

__device__ __forceinline__ uint32_t f2tf32(float x) {
    uint32_t r; asm("cvt.rna.tf32.f32 %0, %1;" : "=r"(r) : "f"(x)); return r;
}
__device__ __forceinline__ void mma_tf32(float* d, const uint32_t* a, const uint32_t* b) {
    asm volatile(
        "mma.sync.aligned.m16n8k8.row.col.f32.tf32.tf32.f32 "
        "{%0,%1,%2,%3}, {%4,%5,%6,%7}, {%8,%9}, {%0,%1,%2,%3};"
        : "+f"(d[0]), "+f"(d[1]), "+f"(d[2]), "+f"(d[3])
        : "r"(a[0]), "r"(a[1]), "r"(a[2]), "r"(a[3]), "r"(b[0]), "r"(b[1]));
}
__device__ __forceinline__ uint32_t hadd2u(uint32_t a, uint32_t b) {
    uint32_t r; asm("add.rn.f16x2 %0,%1,%2;" : "=r"(r) : "r"(a), "r"(b)); return r;
}
__device__ __forceinline__ uint32_t tanh2u(uint32_t a) {
    uint32_t r; asm("tanh.approx.f16x2 %0,%1;" : "=r"(r) : "r"(a)); return r;
}
__device__ __forceinline__ uint32_t hfma2u(uint32_t a, uint32_t b, uint32_t c) {
    uint32_t r; asm("fma.rn.f16x2 %0,%1,%2,%3;" : "=r"(r) : "r"(a), "r"(b), "r"(c)); return r;
}
__device__ __forceinline__ float h2sum(uint32_t u) {
    __half2 h = *reinterpret_cast<__half2*>(&u);
    float2 f = __half22float2(h);
    return f.x + f.y;
}
__device__ __forceinline__ void cp16(uint32_t dst, const void* src) {
    asm volatile("cp.async.cg.shared.global [%0], [%1], 16;" :: "r"(dst), "l"(src));
}
// RNA-round f32 bits for tf32 consumption (HW ignores low 13 bits)
#define RNA32(x) ((x) + 0x1000u)

// ---------------------------------------------------------------------------
// Merged tf32 GEMM, M=8192 N=1024 K=512, cp.async 3-stage.
// job = blockIdx.z: 0 -> projections (g_Pu half2, +bq on n<512)
//                   1 -> Z|S (g_ZS; n<512 tf32-rounded, n>=512 f32)
// CTA tile 128x64, BK=32, 8 warps (4m x 2n), warp tile 32x32.
// ---------------------------------------------------------------------------
#define GSTRIDE (128*36 + 32*72)            // 6912 u32 per stage
#define GSMEM   (3 * GSTRIDE * 4)           // 82944 B

__global__ void __launch_bounds__(256, 2) gemm_k(
    const float* __restrict__ A0, const float* __restrict__ A1,
    const float* __restrict__ Wq, const float* __restrict__ Wc,
    const float* __restrict__ bq, const float* __restrict__ Wout)
{
    constexpr int BM = 128, LDA = 36, LDB = 72;
    extern __shared__ uint32_t sm[];
    const uint32_t sbase = (uint32_t)__cvta_generic_to_shared(sm);

    const int job = blockIdx.z;
    const int m0 = blockIdx.y * BM, n0 = blockIdx.x * 64;
    const int tid = threadIdx.x, warp = tid >> 5, lane = tid & 31;
    const int wm = (warp >> 1) * 32, wn = (warp & 1) * 32;

    const float* B0 = job ? Wout : Wq;
    const float* B1 = job ? (Wout + 512 * 512) : Wc;
    const float* Bp = (n0 < 512) ? (B0 + n0) : (B1 + (n0 - 512));

    const int aidx_r  = tid >> 3, aidx_c4 = (tid & 7) * 4;
    const int bidx_r  = tid >> 4, bidx_c4 = (tid & 15) * 4;

    const float* arow[4];
    #pragma unroll
    for (int it = 0; it < 4; it++) {
        int row = m0 + aidx_r + it * 32;
        arow[it] = ((row < HALF) ? (A0 + (size_t)row * 512)
                                 : (A1 + (size_t)(row - HALF) * 512)) + aidx_c4;
    }
    const uint32_t a_sm_off = (aidx_r * LDA + aidx_c4) * 4;
    const uint32_t b_sm_off = (BM * LDA + bidx_r * LDB + bidx_c4) * 4;

    auto issue = [&](int kt) {
        const uint32_t base = sbase + (kt % 3) * (GSTRIDE * 4);
        #pragma unroll
        for (int it = 0; it < 4; it++)
            cp16(base + a_sm_off + it * (32 * LDA * 4), arow[it] + kt * 32);
        const float* bsrc = Bp + (size_t)(kt * 32 + bidx_r) * 512 + bidx_c4;
        #pragma unroll
        for (int it = 0; it < 2; it++)
            cp16(base + b_sm_off + it * (16 * LDB * 4), bsrc + (size_t)it * 16 * 512);
        asm volatile("cp.async.commit_group;");
    };

    float acc[2][4][4];
    #pragma unroll
    for (int i = 0; i < 2; i++)
        #pragma unroll
        for (int j = 0; j < 4; j++)
            #pragma unroll
            for (int k = 0; k < 4; k++) acc[i][j][k] = 0.f;

    issue(0); issue(1); issue(2);
    asm volatile("cp.async.wait_group 2;");
    __syncthreads();

    for (int kt = 0; kt < 16; kt++) {
        const uint32_t* Ab = sm + (kt % 3) * GSTRIDE;
        const uint32_t* Bb = Ab + BM * LDA;
        #pragma unroll
        for (int ks = 0; ks < 4; ks++) {
            const int kk = ks * 8;
            uint32_t af[2][4], bf[4][2];
            #pragma unroll
            for (int mf = 0; mf < 2; mf++) {
                int r = wm + mf * 16 + (lane >> 2);
                int c = kk + (lane & 3);
                af[mf][0] = RNA32(Ab[r * LDA + c]);
                af[mf][1] = RNA32(Ab[(r + 8) * LDA + c]);
                af[mf][2] = RNA32(Ab[r * LDA + c + 4]);
                af[mf][3] = RNA32(Ab[(r + 8) * LDA + c + 4]);
            }
            #pragma unroll
            for (int nf = 0; nf < 4; nf++) {
                int c = wn + nf * 8 + (lane >> 2);
                int r = kk + (lane & 3);
                bf[nf][0] = RNA32(Bb[r * LDB + c]);
                bf[nf][1] = RNA32(Bb[(r + 4) * LDB + c]);
            }
            #pragma unroll
            for (int mf = 0; mf < 2; mf++)
                #pragma unroll
                for (int nf = 0; nf < 4; nf++)
                    mma_tf32(acc[mf][nf], af[mf], bf[nf]);
        }
        if (kt < 15) {
            __syncthreads();               // all warps done with buf kt%3
            if (kt < 13) {
                issue(kt + 3);             // refills buf kt%3
                asm volatile("cp.async.wait_group 2;");
            } else if (kt == 13) {
                asm volatile("cp.async.wait_group 1;");
            } else {
                asm volatile("cp.async.wait_group 0;");
            }
            __syncthreads();
        }
    }

    // epilogue
    #pragma unroll
    for (int mf = 0; mf < 2; mf++) {
        #pragma unroll
        for (int nf = 0; nf < 4; nf++) {
            int row = m0 + wm + mf * 16 + (lane >> 2);
            int col = n0 + wn + nf * 8 + (lane & 3) * 2;
            if (job == 0) {
                float b0 = 0.f, b1 = 0.f;
                if (n0 < 512) { b0 = bq[col]; b1 = bq[col + 1]; }
                __half2 h0 = __floats2half2_rn(acc[mf][nf][0] + b0, acc[mf][nf][1] + b1);
                __half2 h1 = __floats2half2_rn(acc[mf][nf][2] + b0, acc[mf][nf][3] + b1);
                g_Pu[(size_t)row * 512 + (col >> 1)]       = *reinterpret_cast<uint32_t*>(&h0);
                g_Pu[(size_t)(row + 8) * 512 + (col >> 1)] = *reinterpret_cast<uint32_t*>(&h1);
            } else {
                float2 v0, v1;
                if (n0 < 512) {
                    v0 = make_float2(__uint_as_float(f2tf32(acc[mf][nf][0])),
                                     __uint_as_float(f2tf32(acc[mf][nf][1])));
                    v1 = make_float2(__uint_as_float(f2tf32(acc[mf][nf][2])),
                                     __uint_as_float(f2tf32(acc[mf][nf][3])));
                } else {
                    v0 = make_float2(acc[mf][nf][0], acc[mf][nf][1]);
                    v1 = make_float2(acc[mf][nf][2], acc[mf][nf][3]);
                }
                *(float2*)&g_ZS[(size_t)row * 1024 + col]       = v0;
                *(float2*)&g_ZS[(size_t)(row + 8) * 1024 + col] = v1;
            }
        }
    }
}

// ---------------------------------------------------------------------------
// Fused scores + softmax + align@Z. Lane-per-s layout: lane = s (mod 32),
// no per-(t,s) shuffles. CTA = 16 t-rows of one (call, b). 512 CTAs.
// smem u32 layout: wq2[16][256] | uh2[32][260] | v2s[256] | sc[16][132]
// ---------------------------------------------------------------------------
#define SC_WQ   0
#define SC_UH   4096
#define SC_V    (4096 + 8320)
#define SC_SC   (4096 + 8320 + 256)
#define SC_SMEM ((4096 + 8320 + 256 + 2112) * 4)   // 59136 B

__global__ void __launch_bounds__(256, 2) score_ctx_kernel(const float* __restrict__ v)
{
    extern __shared__ uint32_t smu[];
    uint32_t* wq2 = smu + SC_WQ;     // [16][256]
    uint32_t* uh2 = smu + SC_UH;     // [32][260] padded
    uint32_t* v2s = smu + SC_V;      // [256]
    float*    sc  = (float*)(smu + SC_SC);  // [16][132]
    float*    Zs  = (float*)smu;     // phase B reuse: [16][516] (8256 f ≤ 12416)

    const int bid  = blockIdx.x;
    const int call = bid >> 8;
    const int b    = (bid >> 3) & 31;
    const int t0   = (bid & 7) * 16;
    const int tid  = threadIdx.x, warp = tid >> 5, lane = tid & 31;

    const int srcbase = call * HALF + b * LL + t0;
    const int membase = (1 - call) * HALF + b * LL;

    // stage v as half2
    {
        float2 vv = *(const float2*)(v + 2 * tid);
        __half2 h = __floats2half2_rn(vv.x, vv.y);
        v2s[tid] = *reinterpret_cast<uint32_t*>(&h);
    }
    // stage wq: 16 x 256 u32
    #pragma unroll
    for (int it = 0; it < 4; it++) {
        int idx = tid + it * 256;
        int r = idx >> 6, c4 = (idx & 63) * 4;
        *(uint4*)&wq2[r * 256 + c4] = *(const uint4*)&g_Pu[(size_t)(srcbase + r) * 512 + c4];
    }

    const int tw = warp * 2;
    float s_r[2][4];

    // -------- phase A: scores; lane owns s = st*32 + lane --------
    for (int st = 0; st < 4; st++) {
        __syncthreads();
        #pragma unroll
        for (int it = 0; it < 8; it++) {
            int idx = tid + it * 256;
            int r = idx >> 6, c4 = (idx & 63) * 4;
            *(uint4*)&uh2[r * 260 + c4] =
                *(const uint4*)&g_Pu[(size_t)(membase + st * 32 + r) * 512 + 256 + c4];
        }
        __syncthreads();

        float acc0 = 0.f, acc1 = 0.f;
        const uint32_t* up  = &uh2[lane * 260];
        const uint32_t* w0p = &wq2[tw * 256];
        const uint32_t* w1p = &wq2[(tw + 1) * 256];
        #pragma unroll 8
        for (int j = 0; j < 64; j++) {
            uint4 u  = *(const uint4*)(up + j * 4);
            uint4 vv = *(const uint4*)(v2s + j * 4);
            uint4 w0 = *(const uint4*)(w0p + j * 4);
            uint4 w1 = *(const uint4*)(w1p + j * 4);
            uint32_t a = 0;
            a = hfma2u(vv.x, tanh2u(hadd2u(w0.x, u.x)), a);
            a = hfma2u(vv.y, tanh2u(hadd2u(w0.y, u.y)), a);
            a = hfma2u(vv.z, tanh2u(hadd2u(w0.z, u.z)), a);
            a = hfma2u(vv.w, tanh2u(hadd2u(w0.w, u.w)), a);
            acc0 += h2sum(a);
            a = 0;
            a = hfma2u(vv.x, tanh2u(hadd2u(w1.x, u.x)), a);
            a = hfma2u(vv.y, tanh2u(hadd2u(w1.y, u.y)), a);
            a = hfma2u(vv.z, tanh2u(hadd2u(w1.z, u.z)), a);
            a = hfma2u(vv.w, tanh2u(hadd2u(w1.w, u.w)), a);
            acc1 += h2sum(a);
        }
        s_r[0][st] = acc0;
        s_r[1][st] = acc1;
    }

    // -------- softmax per t-row (one reduction per t) --------
    #pragma unroll
    for (int ti = 0; ti < 2; ti++) {
        float mx = fmaxf(fmaxf(s_r[ti][0], s_r[ti][1]), fmaxf(s_r[ti][2], s_r[ti][3]));
        #pragma unroll
        for (int o = 16; o > 0; o >>= 1)
            mx = fmaxf(mx, __shfl_xor_sync(0xffffffffu, mx, o));
        float e[4], sum = 0.f;
        #pragma unroll
        for (int j = 0; j < 4; j++) { e[j] = __expf(s_r[ti][j] - mx); sum += e[j]; }
        #pragma unroll
        for (int o = 16; o > 0; o >>= 1)
            sum += __shfl_xor_sync(0xffffffffu, sum, o);
        float inv = 1.0f / sum;
        #pragma unroll
        for (int j = 0; j < 4; j++)
            sc[(tw + ti) * 132 + j * 32 + lane] = __uint_as_float(f2tf32(e[j] * inv));
    }

    // -------- phase B: out[16][512] = align @ Z via tf32 mma --------
    float accB[8][4];
    #pragma unroll
    for (int nf = 0; nf < 8; nf++)
        #pragma unroll
        for (int k = 0; k < 4; k++) accB[nf][k] = 0.f;

    const int ncol = warp * 64;
    const int mrow = lane >> 2;

    for (int kc = 0; kc < 8; kc++) {
        __syncthreads();   // frees wq2/uh2 (or prev Zs); orders softmax stores on kc=0
        #pragma unroll
        for (int it = 0; it < 8; it++) {
            int idx = tid + it * 256;
            int r = idx >> 7, c4 = (idx & 127) * 4;
            *(float4*)&Zs[r * 516 + c4] =
                *(const float4*)&g_ZS[(size_t)(membase + kc * 16 + r) * 1024 + c4];
        }
        __syncthreads();

        #pragma unroll
        for (int kf = 0; kf < 2; kf++) {
            const int k8 = kc * 2 + kf;
            const int scol = k8 * 8 + (lane & 3);
            uint32_t af[4];
            af[0] = __float_as_uint(sc[mrow * 132 + scol]);
            af[1] = __float_as_uint(sc[(mrow + 8) * 132 + scol]);
            af[2] = __float_as_uint(sc[mrow * 132 + scol + 4]);
            af[3] = __float_as_uint(sc[(mrow + 8) * 132 + scol + 4]);
            const int rk = kf * 8 + (lane & 3);
            #pragma unroll
            for (int nf = 0; nf < 8; nf++) {
                const int c = ncol + nf * 8 + (lane >> 2);
                uint32_t bf[2];
                bf[0] = __float_as_uint(Zs[rk * 516 + c]);
                bf[1] = __float_as_uint(Zs[(rk + 4) * 516 + c]);
                mma_tf32(accB[nf], af, bf);
            }
        }
    }

    const size_t base = (size_t)call * HALF + (size_t)b * LL + t0;
    #pragma unroll
    for (int nf = 0; nf < 8; nf++) {
        int c = ncol + nf * 8 + (lane & 3) * 2;
        *(float2*)&g_O[(base + mrow) * 512 + c]     = make_float2(accB[nf][0], accB[nf][1]);
        *(float2*)&g_O[(base + mrow + 8) * 512 + c] = make_float2(accB[nf][2], accB[nf][3]);
    }
}

// out = (1-m)*(O0 + S_nobs) + m*(O1 + S_cur) + bout
__global__ __launch_bounds__(256) void combine_kernel(
    const float* __restrict__ mix, const float* __restrict__ bout,
    float* __restrict__ out)
{
    int i = blockIdx.x * 256 + threadIdx.x;
    float m = __ldg(mix);
    int r = i >> 7, c4 = (i & 127) * 4;
    float4 o0 = *(float4*)&g_O[(size_t)r * 512 + c4];
    float4 o1 = *(float4*)&g_O[(size_t)(HALF + r) * 512 + c4];
    float4 s0 = *(const float4*)&g_ZS[(size_t)r * 1024 + 512 + c4];
    float4 s1 = *(const float4*)&g_ZS[(size_t)(HALF + r) * 1024 + 512 + c4];
    float4 bo = *(const float4*)(bout + c4);
    float4 o;
    float w0 = 1.f - m;
    o.x = w0 * (o0.x + s0.x) + m * (o1.x + s1.x) + bo.x;
    o.y = w0 * (o0.y + s0.y) + m * (o1.y + s1.y) + bo.y;
    o.z = w0 * (o0.z + s0.z) + m * (o1.z + s1.z) + bo.z;
    o.w = w0 * (o0.w + s0.w) + m * (o1.w + s1.w) + bo.w;
    *(float4*)(out + (size_t)4 * i) = o;
}

extern "C" void kernel_launch(void* const* d_in, const int* in_sizes, int n_in,
                              void* d_out, int out_size)
{
    const float* cur  = (const float*)d_in[0];
    const float* nobs = (const float*)d_in[1];
    const float* Wq   = (const float*)d_in[2];
    const float* bq   = (const float*)d_in[3];
    const float* Wc   = (const float*)d_in[4];
    const float* v    = (const float*)d_in[5];
    const float* Wout = (const float*)d_in[6];
    const float* bout = (const float*)d_in[7];
    const float* mix  = (const float*)d_in[8];
    float* out = (float*)d_out;

    cudaFuncSetAttribute(gemm_k, cudaFuncAttributeMaxDynamicSharedMemorySize, GSMEM);
    cudaFuncSetAttribute(score_ctx_kernel, cudaFuncAttributeMaxDynamicSharedMemorySize, SC_SMEM);

    // 1) Both GEMMs in one launch: z=0 projections, z=1 Z|S
    gemm_k<<<dim3(16, 64, 2), 256, GSMEM>>>(nobs, cur, Wq, Wc, bq, Wout);
    // 2) scores + softmax + align@Z
    score_ctx_kernel<<<512, 256, SC_SMEM>>>(v);
    // 3) mix + S + bias
    combine_kernel<<<2048, 256>>>(mix, bout, out);
}

// round 4
// speedup vs baseline: 1.5475x; 1.1052x over previous
#include <cuda_runtime.h>
#include <cuda_fp16.h>
#include <cstdint>

#define DD   512
#define LL   128
#define HALF 4096
#define MROWS 8192

// Scratch
__device__ uint32_t g_A [MROWS * 512];    // tf32-rounded [nobs; cur]
__device__ uint32_t g_W [2 * 512 * 1024]; // tf32-rounded B: job0 [Wq|Wc], job1 [Wout_top|Wout_bot]
__device__ uint32_t g_Pu[MROWS * 512];    // half2 projections: cols 0..255 wq, 256..511 uh
__device__ float    g_ZS[MROWS * 1024];   // cols 0..511 Z (tf32), 512..1023 S (f32)
__device__ float    g_O [2 * HALF * 512];

__device__ __forceinline__ uint32_t f2tf32(float x) {
    uint32_t r; asm("cvt.rna.tf32.f32 %0, %1;" : "=r"(r) : "f"(x)); return r;
}
__device__ __forceinline__ void mma_tf32(float* d, const uint32_t* a, const uint32_t* b) {
    asm volatile(
        "mma.sync.aligned.m16n8k8.row.col.f32.tf32.tf32.f32 "
        "{%0,%1,%2,%3}, {%4,%5,%6,%7}, {%8,%9}, {%0,%1,%2,%3};"
        : "+f"(d[0]), "+f"(d[1]), "+f"(d[2]), "+f"(d[3])
        : "r"(a[0]), "r"(a[1]), "r"(a[2]), "r"(a[3]), "r"(b[0]), "r"(b[1]));
}
__device__ __forceinline__ uint32_t hadd2u(uint32_t a, uint32_t b) {
    uint32_t r; asm("add.rn.f16x2 %0,%1,%2;" : "=r"(r) : "r"(a), "r"(b)); return r;
}
__device__ __forceinline__ uint32_t tanh2u(uint32_t a) {
    uint32_t r; asm("tanh.approx.f16x2 %0,%1;" : "=r"(r) : "r"(a)); return r;
}
__device__ __forceinline__ uint32_t hfma2u(uint32_t a, uint32_t b, uint32_t c) {
    uint32_t r; asm("fma.rn.f16x2 %0,%1,%2,%3;" : "=r"(r) : "r"(a), "r"(b), "r"(c)); return r;
}
__device__ __forceinline__ float h2sum(uint32_t u) {
    __half2 h = *reinterpret_cast<__half2*>(&u);
    float2 f = __half22float2(h);
    return f.x + f.y;
}
__device__ __forceinline__ void cp16(uint32_t dst, const void* src) {
    asm volatile("cp.async.cg.shared.global [%0], [%1], 16;" :: "r"(dst), "l"(src));
}

// ---------------------------------------------------------------------------
// Prep: round A and both B matrices to tf32 once.
// items: 1048576 (g_A) + 131072 (g_W job0) + 131072 (g_W job1) float4s
// ---------------------------------------------------------------------------
__global__ __launch_bounds__(256) void prep_k(
    const float* __restrict__ cur, const float* __restrict__ nobs,
    const float* __restrict__ Wq, const float* __restrict__ Wc,
    const float* __restrict__ Wout)
{
    int i = blockIdx.x * 256 + threadIdx.x;
    const float* src;
    uint32_t* dst;
    if (i < 1048576) {
        int idx4 = i * 4;
        int row = idx4 >> 9, col = idx4 & 511;
        src = ((row < HALF) ? nobs + (size_t)row * 512
                            : cur + (size_t)(row - HALF) * 512) + col;
        dst = g_A + idx4;
    } else if (i < 1048576 + 131072) {
        int idx4 = (i - 1048576) * 4;
        int k = idx4 >> 10, n = idx4 & 1023;
        src = (n < 512) ? (Wq + (size_t)k * 512 + n) : (Wc + (size_t)k * 512 + (n - 512));
        dst = g_W + idx4;
    } else {
        int idx4 = (i - 1179648) * 4;
        int k = idx4 >> 10, n = idx4 & 1023;
        src = (n < 512) ? (Wout + (size_t)k * 512 + n)
                        : (Wout + (size_t)(512 + k) * 512 + (n - 512));
        dst = g_W + 512 * 1024 + idx4;
    }
    float4 x = *(const float4*)src;
    uint4 o;
    o.x = f2tf32(x.x); o.y = f2tf32(x.y); o.z = f2tf32(x.z); o.w = f2tf32(x.w);
    *(uint4*)dst = o;
}

// ---------------------------------------------------------------------------
// tf32 GEMM: C[8192,1024] = g_A[8192,512] @ g_W[job][512,1024], cp.async 3-stage.
// job 0 -> g_Pu half2 (+bq on n<512); job 1 -> g_ZS (n<512 tf32, else f32)
// CTA 128x128, BK=32, 8 warps (4m x 2n), warp tile 32x64.
// ---------------------------------------------------------------------------
#define LDA 36
#define LDB 136
#define GSTRIDE (128 * LDA + 32 * LDB)   // 8960 u32 per stage
#define GSMEM   (3 * GSTRIDE * 4)        // 107520 B

__global__ void __launch_bounds__(256, 2) gemm_k(const float* __restrict__ bq)
{
    extern __shared__ uint32_t sm[];
    const uint32_t sbase = (uint32_t)__cvta_generic_to_shared(sm);

    const int job = blockIdx.z;
    const int m0 = blockIdx.y * 128, n0 = blockIdx.x * 128;
    const int tid = threadIdx.x, warp = tid >> 5, lane = tid & 31;
    const int wm = (warp >> 1) * 32, wn = (warp & 1) * 64;

    const uint32_t* Bg = g_W + (size_t)job * 512 * 1024;

    // staging indices
    const int a_r = tid >> 3, a_c4 = (tid & 7) * 4;     // +32 rows per it (4 its)
    const int b_r = tid >> 5, b_c4 = (tid & 31) * 4;    // +8 rows per it (4 its)
    const uint32_t a_off = (a_r * LDA + a_c4) * 4;
    const uint32_t b_off = (128 * LDA + b_r * LDB + b_c4) * 4;

    auto issue = [&](int kt) {
        const uint32_t base = sbase + (kt % 3) * (GSTRIDE * 4);
        const uint32_t* asrc = g_A + (size_t)(m0 + a_r) * 512 + kt * 32 + a_c4;
        #pragma unroll
        for (int it = 0; it < 4; it++)
            cp16(base + a_off + it * (32 * LDA * 4), asrc + (size_t)it * 32 * 512);
        const uint32_t* bsrc = Bg + (size_t)(kt * 32 + b_r) * 1024 + n0 + b_c4;
        #pragma unroll
        for (int it = 0; it < 4; it++)
            cp16(base + b_off + it * (8 * LDB * 4), bsrc + (size_t)it * 8 * 1024);
        asm volatile("cp.async.commit_group;");
    };

    float acc[2][8][4];
    #pragma unroll
    for (int i = 0; i < 2; i++)
        #pragma unroll
        for (int j = 0; j < 8; j++)
            #pragma unroll
            for (int k = 0; k < 4; k++) acc[i][j][k] = 0.f;

    issue(0); issue(1); issue(2);
    asm volatile("cp.async.wait_group 2;");
    __syncthreads();

    for (int kt = 0; kt < 16; kt++) {
        const uint32_t* Ab = sm + (kt % 3) * GSTRIDE;
        const uint32_t* Bb = Ab + 128 * LDA;
        #pragma unroll
        for (int ks = 0; ks < 4; ks++) {
            const int kk = ks * 8;
            uint32_t af[2][4];
            #pragma unroll
            for (int mf = 0; mf < 2; mf++) {
                int r = wm + mf * 16 + (lane >> 2);
                int c = kk + (lane & 3);
                af[mf][0] = Ab[r * LDA + c];
                af[mf][1] = Ab[(r + 8) * LDA + c];
                af[mf][2] = Ab[r * LDA + c + 4];
                af[mf][3] = Ab[(r + 8) * LDA + c + 4];
            }
            #pragma unroll
            for (int nf = 0; nf < 8; nf++) {
                int c = wn + nf * 8 + (lane >> 2);
                int r = kk + (lane & 3);
                uint32_t bf[2];
                bf[0] = Bb[r * LDB + c];
                bf[1] = Bb[(r + 4) * LDB + c];
                mma_tf32(acc[0][nf], af[0], bf);
                mma_tf32(acc[1][nf], af[1], bf);
            }
        }
        if (kt < 15) {
            __syncthreads();
            if (kt < 13) {
                issue(kt + 3);
                asm volatile("cp.async.wait_group 2;");
            } else if (kt == 13) {
                asm volatile("cp.async.wait_group 1;");
            } else {
                asm volatile("cp.async.wait_group 0;");
            }
            __syncthreads();
        }
    }

    // epilogue
    #pragma unroll
    for (int mf = 0; mf < 2; mf++) {
        #pragma unroll
        for (int nf = 0; nf < 8; nf++) {
            int row = m0 + wm + mf * 16 + (lane >> 2);
            int col = n0 + wn + nf * 8 + (lane & 3) * 2;
            if (job == 0) {
                float b0 = 0.f, b1 = 0.f;
                if (col < 512) { b0 = bq[col]; b1 = bq[col + 1]; }
                __half2 h0 = __floats2half2_rn(acc[mf][nf][0] + b0, acc[mf][nf][1] + b1);
                __half2 h1 = __floats2half2_rn(acc[mf][nf][2] + b0, acc[mf][nf][3] + b1);
                g_Pu[(size_t)row * 512 + (col >> 1)]       = *reinterpret_cast<uint32_t*>(&h0);
                g_Pu[(size_t)(row + 8) * 512 + (col >> 1)] = *reinterpret_cast<uint32_t*>(&h1);
            } else {
                float2 v0, v1;
                if (col < 512) {
                    v0 = make_float2(__uint_as_float(f2tf32(acc[mf][nf][0])),
                                     __uint_as_float(f2tf32(acc[mf][nf][1])));
                    v1 = make_float2(__uint_as_float(f2tf32(acc[mf][nf][2])),
                                     __uint_as_float(f2tf32(acc[mf][nf][3])));
                } else {
                    v0 = make_float2(acc[mf][nf][0], acc[mf][nf][1]);
                    v1 = make_float2(acc[mf][nf][2], acc[mf][nf][3]);
                }
                *(float2*)&g_ZS[(size_t)row * 1024 + col]       = v0;
                *(float2*)&g_ZS[(size_t)(row + 8) * 1024 + col] = v1;
            }
        }
    }
}

// ---------------------------------------------------------------------------
// Fused scores + softmax + align@Z. Lane = s (mod 32); warp = 4 t-rows;
// CTA = 32 t-rows of one (call, b). 256 CTAs.
// smem u32: wq2[32][256] | uh2[32][260] | v2s[256] | sc[32][132]f
// ---------------------------------------------------------------------------
#define SC_WQ   0
#define SC_UH   8192
#define SC_V    (8192 + 8320)
#define SC_SC   (8192 + 8320 + 256)
#define SC_SMEM ((8192 + 8320 + 256 + 32 * 132) * 4)   // 83968 B

__global__ void __launch_bounds__(256, 2) score_ctx_kernel(const float* __restrict__ v)
{
    extern __shared__ uint32_t smu[];
    uint32_t* wq2 = smu + SC_WQ;            // [32][256]
    uint32_t* uh2 = smu + SC_UH;            // [32][260]
    uint32_t* v2s = smu + SC_V;             // [256]
    float*    sc  = (float*)(smu + SC_SC);  // [32][132]
    float*    Zs  = (float*)smu;            // phase B reuse: [16][516] = 8256 f (fits in wq2+uh2)

    const int bid  = blockIdx.x;            // 256 CTAs
    const int call = bid >> 7;
    const int b    = (bid >> 2) & 31;
    const int t0   = (bid & 3) * 32;
    const int tid  = threadIdx.x, warp = tid >> 5, lane = tid & 31;

    const int srcbase = call * HALF + b * LL + t0;
    const int membase = (1 - call) * HALF + b * LL;

    // stage v as half2
    {
        float2 vv = *(const float2*)(v + 2 * tid);
        __half2 h = __floats2half2_rn(vv.x, vv.y);
        v2s[tid] = *reinterpret_cast<uint32_t*>(&h);
    }
    // stage wq: 32 x 256 u32 (2048 uint4)
    #pragma unroll
    for (int it = 0; it < 8; it++) {
        int idx = tid + it * 256;
        int r = idx >> 6, c4 = (idx & 63) * 4;
        *(uint4*)&wq2[r * 256 + c4] = *(const uint4*)&g_Pu[(size_t)(srcbase + r) * 512 + c4];
    }

    const int tw = warp * 4;
    float s_r[4][4];

    // -------- phase A: scores; lane owns s = st*32 + lane; warp owns 4 t-rows
    for (int st = 0; st < 4; st++) {
        __syncthreads();
        #pragma unroll
        for (int it = 0; it < 8; it++) {
            int idx = tid + it * 256;
            int r = idx >> 6, c4 = (idx & 63) * 4;
            *(uint4*)&uh2[r * 260 + c4] =
                *(const uint4*)&g_Pu[(size_t)(membase + st * 32 + r) * 512 + 256 + c4];
        }
        __syncthreads();

        float a0 = 0.f, a1 = 0.f, a2 = 0.f, a3 = 0.f;
        const uint32_t* up  = &uh2[lane * 260];
        const uint32_t* w0p = &wq2[tw * 256];
        const uint32_t* w1p = w0p + 256;
        const uint32_t* w2p = w0p + 512;
        const uint32_t* w3p = w0p + 768;
        #pragma unroll 4
        for (int j = 0; j < 64; j++) {
            uint4 u  = *(const uint4*)(up + j * 4);
            uint4 vv = *(const uint4*)(v2s + j * 4);
            uint4 w;
            uint32_t c2;
            w = *(const uint4*)(w0p + j * 4);
            c2 = 0;
            c2 = hfma2u(vv.x, tanh2u(hadd2u(w.x, u.x)), c2);
            c2 = hfma2u(vv.y, tanh2u(hadd2u(w.y, u.y)), c2);
            c2 = hfma2u(vv.z, tanh2u(hadd2u(w.z, u.z)), c2);
            c2 = hfma2u(vv.w, tanh2u(hadd2u(w.w, u.w)), c2);
            a0 += h2sum(c2);
            w = *(const uint4*)(w1p + j * 4);
            c2 = 0;
            c2 = hfma2u(vv.x, tanh2u(hadd2u(w.x, u.x)), c2);
            c2 = hfma2u(vv.y, tanh2u(hadd2u(w.y, u.y)), c2);
            c2 = hfma2u(vv.z, tanh2u(hadd2u(w.z, u.z)), c2);
            c2 = hfma2u(vv.w, tanh2u(hadd2u(w.w, u.w)), c2);
            a1 += h2sum(c2);
            w = *(const uint4*)(w2p + j * 4);
            c2 = 0;
            c2 = hfma2u(vv.x, tanh2u(hadd2u(w.x, u.x)), c2);
            c2 = hfma2u(vv.y, tanh2u(hadd2u(w.y, u.y)), c2);
            c2 = hfma2u(vv.z, tanh2u(hadd2u(w.z, u.z)), c2);
            c2 = hfma2u(vv.w, tanh2u(hadd2u(w.w, u.w)), c2);
            a2 += h2sum(c2);
            w = *(const uint4*)(w3p + j * 4);
            c2 = 0;
            c2 = hfma2u(vv.x, tanh2u(hadd2u(w.x, u.x)), c2);
            c2 = hfma2u(vv.y, tanh2u(hadd2u(w.y, u.y)), c2);
            c2 = hfma2u(vv.z, tanh2u(hadd2u(w.z, u.z)), c2);
            c2 = hfma2u(vv.w, tanh2u(hadd2u(w.w, u.w)), c2);
            a3 += h2sum(c2);
        }
        s_r[0][st] = a0; s_r[1][st] = a1; s_r[2][st] = a2; s_r[3][st] = a3;
    }

    // -------- softmax per t-row --------
    #pragma unroll
    for (int ti = 0; ti < 4; ti++) {
        float mx = fmaxf(fmaxf(s_r[ti][0], s_r[ti][1]), fmaxf(s_r[ti][2], s_r[ti][3]));
        #pragma unroll
        for (int o = 16; o > 0; o >>= 1)
            mx = fmaxf(mx, __shfl_xor_sync(0xffffffffu, mx, o));
        float e[4], sum = 0.f;
        #pragma unroll
        for (int j = 0; j < 4; j++) { e[j] = __expf(s_r[ti][j] - mx); sum += e[j]; }
        #pragma unroll
        for (int o = 16; o > 0; o >>= 1)
            sum += __shfl_xor_sync(0xffffffffu, sum, o);
        float inv = 1.0f / sum;
        #pragma unroll
        for (int j = 0; j < 4; j++)
            sc[(tw + ti) * 132 + j * 32 + lane] = __uint_as_float(f2tf32(e[j] * inv));
    }

    // -------- phase B: out[32][512] = align @ Z via tf32 mma --------
    float accB[2][8][4];
    #pragma unroll
    for (int mf = 0; mf < 2; mf++)
        #pragma unroll
        for (int nf = 0; nf < 8; nf++)
            #pragma unroll
            for (int k = 0; k < 4; k++) accB[mf][nf][k] = 0.f;

    const int ncol = warp * 64;
    const int mrow = lane >> 2;

    for (int kc = 0; kc < 8; kc++) {
        __syncthreads();   // frees wq2/uh2 (or prev Zs); orders softmax on kc=0
        #pragma unroll
        for (int it = 0; it < 8; it++) {
            int idx = tid + it * 256;
            int r = idx >> 7, c4 = (idx & 127) * 4;
            *(float4*)&Zs[r * 516 + c4] =
                *(const float4*)&g_ZS[(size_t)(membase + kc * 16 + r) * 1024 + c4];
        }
        __syncthreads();

        #pragma unroll
        for (int kf = 0; kf < 2; kf++) {
            const int scol = (kc * 2 + kf) * 8 + (lane & 3);
            uint32_t af[2][4];
            #pragma unroll
            for (int mf = 0; mf < 2; mf++) {
                int mr = mf * 16 + mrow;
                af[mf][0] = __float_as_uint(sc[mr * 132 + scol]);
                af[mf][1] = __float_as_uint(sc[(mr + 8) * 132 + scol]);
                af[mf][2] = __float_as_uint(sc[mr * 132 + scol + 4]);
                af[mf][3] = __float_as_uint(sc[(mr + 8) * 132 + scol + 4]);
            }
            const int rk = kf * 8 + (lane & 3);
            #pragma unroll
            for (int nf = 0; nf < 8; nf++) {
                const int c = ncol + nf * 8 + mrow;
                uint32_t bf[2];
                bf[0] = __float_as_uint(Zs[rk * 516 + c]);
                bf[1] = __float_as_uint(Zs[(rk + 4) * 516 + c]);
                mma_tf32(accB[0][nf], af[0], bf);
                mma_tf32(accB[1][nf], af[1], bf);
            }
        }
    }

    const size_t base = (size_t)call * HALF + (size_t)b * LL + t0;
    #pragma unroll
    for (int mf = 0; mf < 2; mf++) {
        #pragma unroll
        for (int nf = 0; nf < 8; nf++) {
            int c = ncol + nf * 8 + (lane & 3) * 2;
            size_t row = base + mf * 16 + mrow;
            *(float2*)&g_O[row * 512 + c]       = make_float2(accB[mf][nf][0], accB[mf][nf][1]);
            *(float2*)&g_O[(row + 8) * 512 + c] = make_float2(accB[mf][nf][2], accB[mf][nf][3]);
        }
    }
}

// out = (1-m)*(O0 + S_nobs) + m*(O1 + S_cur) + bout
__global__ __launch_bounds__(256) void combine_kernel(
    const float* __restrict__ mix, const float* __restrict__ bout,
    float* __restrict__ out)
{
    int i = blockIdx.x * 256 + threadIdx.x;
    float m = __ldg(mix);
    int r = i >> 7, c4 = (i & 127) * 4;
    float4 o0 = *(float4*)&g_O[(size_t)r * 512 + c4];
    float4 o1 = *(float4*)&g_O[(size_t)(HALF + r) * 512 + c4];
    float4 s0 = *(const float4*)&g_ZS[(size_t)r * 1024 + 512 + c4];
    float4 s1 = *(const float4*)&g_ZS[(size_t)(HALF + r) * 1024 + 512 + c4];
    float4 bo = *(const float4*)(bout + c4);
    float4 o;
    float w0 = 1.f - m;
    o.x = w0 * (o0.x + s0.x) + m * (o1.x + s1.x) + bo.x;
    o.y = w0 * (o0.y + s0.y) + m * (o1.y + s1.y) + bo.y;
    o.z = w0 * (o0.z + s0.z) + m * (o1.z + s1.z) + bo.z;
    o.w = w0 * (o0.w + s0.w) + m * (o1.w + s1.w) + bo.w;
    *(float4*)(out + (size_t)4 * i) = o;
}

extern "C" void kernel_launch(void* const* d_in, const int* in_sizes, int n_in,
                              void* d_out, int out_size)
{
    const float* cur  = (const float*)d_in[0];
    const float* nobs = (const float*)d_in[1];
    const float* Wq   = (const float*)d_in[2];
    const float* bq   = (const float*)d_in[3];
    const float* Wc   = (const float*)d_in[4];
    const float* v    = (const float*)d_in[5];
    const float* Wout = (const float*)d_in[6];
    const float* bout = (const float*)d_in[7];
    const float* mix  = (const float*)d_in[8];
    float* out = (float*)d_out;

    cudaFuncSetAttribute(gemm_k, cudaFuncAttributeMaxDynamicSharedMemorySize, GSMEM);
    cudaFuncSetAttribute(score_ctx_kernel, cudaFuncAttributeMaxDynamicSharedMemorySize, SC_SMEM);

    // 0) tf32 pre-round of A and both B panels
    prep_k<<<5120, 256>>>(cur, nobs, Wq, Wc, Wout);
    // 1) Both GEMMs: z=0 projections -> g_Pu, z=1 Z|S -> g_ZS
    gemm_k<<<dim3(8, 64, 2), 256, GSMEM>>>(bq);
    // 2) scores + softmax + align@Z
    score_ctx_kernel<<<256, 256, SC_SMEM>>>(v);
    // 3) mix + S + bias
    combine_kernel<<<2048, 256>>>(mix, bout, out);
}